// round 5
// baseline (speedup 1.0000x reference)
#include <cuda_runtime.h>

#define NN   200000
#define DIM  64
#define NV   (NN * DIM)
#define EMAX 1250000
#define ALPHA 0.25f
#define NB_SCAN ((NN + 1023) / 1024)   // 196

// Scratch (device globals — no allocation allowed).
// NOTE: never pass these symbols from host code; select inside kernels.
__device__ float g_x1[NV];
__device__ float g_x2[NV];
__device__ float g_out[NV];
__device__ float g_dis[NN];
__device__ int   g_deg[NN];
__device__ int   g_off[NN];
__device__ int   g_cur[NN];
__device__ int   g_bsum[NB_SCAN];
__device__ int   g_bpre[NB_SCAN];
__device__ int   g_src[EMAX];
__device__ float g_wgt[EMAX];

// ---- degree / normalization ----
__global__ void k_deg0() {
    int i = blockIdx.x * blockDim.x + threadIdx.x;
    if (i < NN) { g_deg[i] = 0; g_cur[i] = 0; }
}

__global__ void k_count(const int* __restrict__ col, int E) {
    int i = blockIdx.x * blockDim.x + threadIdx.x;
    if (i < E) atomicAdd(&g_deg[col[i]], 1);
}

__global__ void k_dis() {
    int i = blockIdx.x * blockDim.x + threadIdx.x;
    if (i < NN) {
        int d = g_deg[i];
        g_dis[i] = (d > 0) ? rsqrtf((float)d) : 0.f;
    }
}

// ---- exclusive scan of degrees ----
__global__ void k_scan1() {
    __shared__ int s[1024];
    int tid = threadIdx.x;
    int i = blockIdx.x * 1024 + tid;
    int v = (i < NN) ? g_deg[i] : 0;
    s[tid] = v;
    __syncthreads();
    #pragma unroll
    for (int o = 1; o < 1024; o <<= 1) {
        int t = (tid >= o) ? s[tid - o] : 0;
        __syncthreads();
        s[tid] += t;
        __syncthreads();
    }
    if (i < NN) g_off[i] = s[tid] - v;
    if (tid == 1023) g_bsum[blockIdx.x] = s[1023];
}

__global__ void k_scan2() {
    __shared__ int s[256];
    int tid = threadIdx.x;
    int v = (tid < NB_SCAN) ? g_bsum[tid] : 0;
    s[tid] = v;
    __syncthreads();
    #pragma unroll
    for (int o = 1; o < 256; o <<= 1) {
        int t = (tid >= o) ? s[tid - o] : 0;
        __syncthreads();
        s[tid] += t;
        __syncthreads();
    }
    if (tid < NB_SCAN) g_bpre[tid] = s[tid] - v;
}

__global__ void k_off_final() {
    int i = blockIdx.x * blockDim.x + threadIdx.x;
    if (i < NN) g_off[i] += g_bpre[i >> 10];
}

// ---- CSR fill: slot per (dst, edge) with precomputed weight ----
__global__ void k_fill(const int* __restrict__ row, const int* __restrict__ col, int E) {
    int e = blockIdx.x * blockDim.x + threadIdx.x;
    if (e >= E) return;
    int r = __ldg(row + e);
    int c = __ldg(col + e);
    int slot = __ldg(g_off + c) + atomicAdd(&g_cur[c], 1);
    g_src[slot] = r;
    g_wgt[slot] = __ldg((const float*)g_dis + r) * __ldg((const float*)g_dis + c);
}

// ---- gather SpMM: ONE WARP PER NODE, float2 per lane.
// No intra-warp divergence (single loop bound per warp); 4 independent
// accumulators break the FMA dependency chain so the 4 gathers in the
// unrolled body are fully overlapped.
// layer 0: emb -> g_x1 ; layer 1: g_x1 -> g_x2
__global__ void k_gather(const float* __restrict__ emb, int layer) {
    int t = blockIdx.x * blockDim.x + threadIdx.x;
    int node = t >> 5;
    int lane = t & 31;
    if (node >= NN) return;

    const float2* x  = (layer == 0) ? (const float2*)emb  : (const float2*)g_x1;
    float2*       xn = (layer == 0) ? (float2*)g_x1 : (float2*)g_x2;

    int beg = __ldg(g_off + node);
    int deg = __ldg(g_deg + node);

    float2 a0 = make_float2(0.f, 0.f), a1 = a0, a2 = a0, a3 = a0;

    int k = 0;
    for (; k + 4 <= deg; k += 4) {
        int r0 = __ldg(g_src + beg + k);
        int r1 = __ldg(g_src + beg + k + 1);
        int r2 = __ldg(g_src + beg + k + 2);
        int r3 = __ldg(g_src + beg + k + 3);
        float w0 = __ldg(g_wgt + beg + k);
        float w1 = __ldg(g_wgt + beg + k + 1);
        float w2 = __ldg(g_wgt + beg + k + 2);
        float w3 = __ldg(g_wgt + beg + k + 3);
        float2 v0 = __ldg(x + (size_t)r0 * 32 + lane);
        float2 v1 = __ldg(x + (size_t)r1 * 32 + lane);
        float2 v2 = __ldg(x + (size_t)r2 * 32 + lane);
        float2 v3 = __ldg(x + (size_t)r3 * 32 + lane);
        a0.x += w0 * v0.x; a0.y += w0 * v0.y;
        a1.x += w1 * v1.x; a1.y += w1 * v1.y;
        a2.x += w2 * v2.x; a2.y += w2 * v2.y;
        a3.x += w3 * v3.x; a3.y += w3 * v3.y;
    }
    if (k + 2 <= deg) {
        int r0 = __ldg(g_src + beg + k);
        int r1 = __ldg(g_src + beg + k + 1);
        float w0 = __ldg(g_wgt + beg + k);
        float w1 = __ldg(g_wgt + beg + k + 1);
        float2 v0 = __ldg(x + (size_t)r0 * 32 + lane);
        float2 v1 = __ldg(x + (size_t)r1 * 32 + lane);
        a0.x += w0 * v0.x; a0.y += w0 * v0.y;
        a1.x += w1 * v1.x; a1.y += w1 * v1.y;
        k += 2;
    }
    if (k < deg) {
        int r0 = __ldg(g_src + beg + k);
        float w0 = __ldg(g_wgt + beg + k);
        float2 v0 = __ldg(x + (size_t)r0 * 32 + lane);
        a2.x += w0 * v0.x; a2.y += w0 * v0.y;
    }

    float2 acc;
    acc.x = (a0.x + a1.x) + (a2.x + a3.x);
    acc.y = (a0.y + a1.y) + (a2.y + a3.y);
    xn[(size_t)node * 32 + lane] = acc;
}

// ---- final layer fused with alpha-combine: out = 0.25*(emb+x1+x2+gather(x2))
__global__ void k_gather_final(const float* __restrict__ emb) {
    int t = blockIdx.x * blockDim.x + threadIdx.x;
    int node = t >> 5;
    int lane = t & 31;
    if (node >= NN) return;

    const float2* x = (const float2*)g_x2;
    int beg = __ldg(g_off + node);
    int deg = __ldg(g_deg + node);

    float2 a0 = make_float2(0.f, 0.f), a1 = a0, a2 = a0, a3 = a0;

    int k = 0;
    for (; k + 4 <= deg; k += 4) {
        int r0 = __ldg(g_src + beg + k);
        int r1 = __ldg(g_src + beg + k + 1);
        int r2 = __ldg(g_src + beg + k + 2);
        int r3 = __ldg(g_src + beg + k + 3);
        float w0 = __ldg(g_wgt + beg + k);
        float w1 = __ldg(g_wgt + beg + k + 1);
        float w2 = __ldg(g_wgt + beg + k + 2);
        float w3 = __ldg(g_wgt + beg + k + 3);
        float2 v0 = __ldg(x + (size_t)r0 * 32 + lane);
        float2 v1 = __ldg(x + (size_t)r1 * 32 + lane);
        float2 v2 = __ldg(x + (size_t)r2 * 32 + lane);
        float2 v3 = __ldg(x + (size_t)r3 * 32 + lane);
        a0.x += w0 * v0.x; a0.y += w0 * v0.y;
        a1.x += w1 * v1.x; a1.y += w1 * v1.y;
        a2.x += w2 * v2.x; a2.y += w2 * v2.y;
        a3.x += w3 * v3.x; a3.y += w3 * v3.y;
    }
    if (k + 2 <= deg) {
        int r0 = __ldg(g_src + beg + k);
        int r1 = __ldg(g_src + beg + k + 1);
        float w0 = __ldg(g_wgt + beg + k);
        float w1 = __ldg(g_wgt + beg + k + 1);
        float2 v0 = __ldg(x + (size_t)r0 * 32 + lane);
        float2 v1 = __ldg(x + (size_t)r1 * 32 + lane);
        a0.x += w0 * v0.x; a0.y += w0 * v0.y;
        a1.x += w1 * v1.x; a1.y += w1 * v1.y;
        k += 2;
    }
    if (k < deg) {
        int r0 = __ldg(g_src + beg + k);
        float w0 = __ldg(g_wgt + beg + k);
        float2 v0 = __ldg(x + (size_t)r0 * 32 + lane);
        a2.x += w0 * v0.x; a2.y += w0 * v0.y;
    }

    size_t idx = (size_t)node * 32 + lane;
    float2 a = __ldg((const float2*)emb + idx);
    float2 b = ((const float2*)g_x1)[idx];
    float2 c = ((const float2*)g_x2)[idx];
    float2 o;
    o.x = ALPHA * (a.x + b.x + c.x + ((a0.x + a1.x) + (a2.x + a3.x)));
    o.y = ALPHA * (a.y + b.y + c.y + ((a0.y + a1.y) + (a2.y + a3.y)));
    ((float2*)g_out)[idx] = o;
}

// ---- scoring: 16 lanes per (user,item) pair, float4 loads ----
__global__ void k_score(const int* __restrict__ batch, float* __restrict__ out, int P) {
    int t = blockIdx.x * blockDim.x + threadIdx.x;
    int p = t >> 4;
    int lane = t & 15;
    if (p >= P) return;
    int u = __ldg(batch + 3 * p);
    int v = __ldg(batch + 3 * p + 1);
    float4 a = __ldg((const float4*)g_out + (size_t)u * 16 + lane);
    float4 b = __ldg((const float4*)g_out + (size_t)v * 16 + lane);
    float s = a.x * b.x + a.y * b.y + a.z * b.z + a.w * b.w;
    #pragma unroll
    for (int o = 8; o; o >>= 1) s += __shfl_xor_sync(0xFFFFFFFFu, s, o);
    if (lane == 0) out[p] = s;
}

extern "C" void kernel_launch(void* const* d_in, const int* in_sizes, int n_in,
                              void* d_out, int out_size) {
    const float* emb   = (const float*)d_in[0];
    const int*   ei    = (const int*)d_in[1];
    const int*   batch = (const int*)d_in[2];
    float*       out   = (float*)d_out;

    int E = in_sizes[1] / 2;
    const int* row = ei;
    const int* col = ei + E;
    int P = in_sizes[2] / 3;

    k_deg0<<<(NN + 255) / 256, 256>>>();
    k_count<<<(E + 255) / 256, 256>>>(col, E);
    k_dis<<<(NN + 255) / 256, 256>>>();
    k_scan1<<<NB_SCAN, 1024>>>();
    k_scan2<<<1, 256>>>();
    k_off_final<<<(NN + 255) / 256, 256>>>();
    k_fill<<<(E + 255) / 256, 256>>>(row, col, E);

    long long gthreads = (long long)NN * 32;
    int gblocks = (int)((gthreads + 255) / 256);
    k_gather<<<gblocks, 256>>>(emb, 0);
    k_gather<<<gblocks, 256>>>(emb, 1);
    k_gather_final<<<gblocks, 256>>>(emb);

    long long sthreads = (long long)P * 16;
    k_score<<<(int)((sthreads + 255) / 256), 256>>>(batch, out, P);
}